// round 15
// baseline (speedup 1.0000x reference)
#include <cuda_runtime.h>
#include <cuda_bf16.h>
#include <cuda_fp16.h>
#include <math.h>
#include <stdint.h>
#include <stddef.h>

#define NMAX 200000
#define EMAX 600000
#define HIDC 128
#define NH 8
#define HD 16

// A smem tile: 256 rows x 136 fp16 (272 B/row, +16B pad -> conflict-free ldmatrix)
// B images: 128 x 136 fp16 (hi) + 128 x 136 (lo), double buffered
#define ROWB 272
#define ATILE 69632        // 256 * 272
#define HALFB 34816        // 128 * 272 (one B image)
#define SM_A  0
#define SM_B0 69632
#define SM_B1 139264
#define SMEM_TOT 208896

// ---------------- scratch (device globals; no runtime allocation) ----------------
__device__ __half g_xA[2][(size_t)NMAX * HIDC];
__device__ __half g_xB[2][(size_t)NMAX * HIDC];
__device__ __half g_qh[2][(size_t)NMAX * HIDC];
__device__ __half g_kh[2][(size_t)NMAX * HIDC];
__device__ __half g_vh[2][(size_t)NMAX * HIDC];
__device__ __half g_att[2][(size_t)NMAX * HIDC];
// CSR (built once per launch; edges constant across layers)
__device__ int g_deg[2][NMAX];
__device__ int g_off[2][NMAX + 1];
__device__ int g_cur[2][NMAX];
__device__ int g_csrc[2][EMAX];
__device__ int g_bsum[2][1024];
// prepped weights: 19 matrices, each 69632 B (fp16 hi image 34816 + fp16 lo image 34816)
__device__ uint4 g_wblob[19][4352];
__device__ float g_biasP[19][128];

// ---------------- helpers ----------------
__device__ __forceinline__ uint32_t smem_u32(const void* p) {
    uint32_t a;
    asm("{ .reg .u64 t; cvta.to.shared.u64 t, %1; cvt.u32.u64 %0, t; }" : "=r"(a) : "l"(p));
    return a;
}

#define LDM4(r0, r1, r2, r3, addr) \
    asm volatile("ldmatrix.sync.aligned.m8n8.x4.shared.b16 {%0,%1,%2,%3}, [%4];" \
                 : "=r"(r0), "=r"(r1), "=r"(r2), "=r"(r3) : "r"(addr))

#define MMA16816(c, a, b0, b1) \
    asm volatile("mma.sync.aligned.m16n8k16.row.col.f32.f16.f16.f32 " \
                 "{%0,%1,%2,%3},{%4,%5,%6,%7},{%8,%9},{%0,%1,%2,%3};" \
                 : "+f"((c)[0]), "+f"((c)[1]), "+f"((c)[2]), "+f"((c)[3]) \
                 : "r"((a)[0]), "r"((a)[1]), "r"((a)[2]), "r"((a)[3]), \
                   "r"(b0), "r"(b1))

#define CP_ASYNC16(dst, src) \
    asm volatile("cp.async.cg.shared.global [%0], [%1], 16;" :: "r"(dst), "l"(src))
#define CP_COMMIT() asm volatile("cp.async.commit_group;" ::: "memory")
#define CP_WAIT0()  asm volatile("cp.async.wait_group 0;" ::: "memory")

__device__ __forceinline__ float gelu_f(float x) {
    return 0.5f * x * (1.0f + erff(x * 0.7071067811865475f));
}

// ---------------- weight prep: compose rel/p-scale, transpose to [n][k], fp16 hi/lo split ----------------
struct PrepJob {
    const float* W;    // [kin x nout] row-major
    const float* b;    // [nout]
    const float* rel;  // [8,16,16] or null
    const float* psc;  // [8] or null (also multiplies 0.25 = 1/sqrt(D))
    int kin;
    int nout;
    uint4* blob;
    float* bias;
};
struct PrepArgs { PrepJob j[19]; };

__global__ void prep_kernel(PrepArgs pa) {
    __shared__ float rel_s[2048];
    __shared__ float bsrc[128];
    const PrepJob jb = pa.j[blockIdx.x];
    const int tid = threadIdx.x;
    const bool hasrel = (jb.rel != nullptr);
    if (hasrel)
        for (int i = tid; i < 2048; i += 256) rel_s[i] = jb.rel[i];
    for (int i = tid; i < 128; i += 256) bsrc[i] = (i < jb.nout) ? jb.b[i] : 0.f;
    __syncthreads();

    char* blob = (char*)jb.blob;
    for (int i = tid; i < 16384; i += 256) {
        int k = i >> 7;
        int n = i & 127;
        float v = 0.f;
        if (k < jb.kin && n < jb.nout) {
            if (hasrel) {
                int h = n >> 4, e = n & 15;
                const float* wrow = jb.W + (size_t)k * 128 + h * 16;
                const float* rr = rel_s + h * 256 + e;
                float s = 0.f;
#pragma unroll
                for (int d = 0; d < 16; ++d) s = fmaf(wrow[d], rr[d * 16], s);
                v = s;
            } else {
                v = jb.W[(size_t)k * jb.nout + n];
            }
            if (jb.psc) v *= jb.psc[n >> 4] * 0.25f;
        }
        __half hi = __float2half(v);
        __half lo = __float2half(v - __half2float(hi));
        uint32_t off = (uint32_t)n * ROWB + (uint32_t)k * 2;  // B stored [n][k]
        *reinterpret_cast<__half*>(blob + off) = hi;
        *reinterpret_cast<__half*>(blob + HALFB + off) = lo;
    }
    if (tid < 128) {
        int n = tid;
        float bc;
        if (hasrel) {
            int h = n >> 4, e = n & 15;
            float s = 0.f;
#pragma unroll
            for (int d = 0; d < 16; ++d) s = fmaf(bsrc[h * 16 + d], rel_s[h * 256 + d * 16 + e], s);
            bc = s;
        } else {
            bc = bsrc[n];
        }
        if (jb.psc) bc *= jb.psc[n >> 4] * 0.25f;
        jb.bias[n] = bc;
    }
}

// ---------------- fp16 A x fp16(hi/lo) B HMMA GEMM ----------------
// 256x128 CTA tile, 512 threads = 16 warps in 8x2 grid (warp tile 32 rows x 64 cols).
// cp.async double-buffered B. Two problem halves per grid (offset arithmetic).
// MODE: 0 plain, 1 relu, 3 pre-gelu on A + sigmoid-skip blend with fp16 xold
// OUTH: 1 -> fp16 outputs; INH: 1 -> A is fp16 (aOff counted in halves)
template <int MODE, int OUTH, int INH>
__global__ void __launch_bounds__(512, 1)
gemm_hmma(const float* A, int kin,
          const uint4* blob, const float* bias,
          int nmat, int nout,
          float* c0, float* c1, float* c2,
          int nrows, const float* xold, const float* skipp,
          int ntile0, int kinB, ptrdiff_t aOff, size_t blobOff, int biasOff,
          size_t cOff, int skipOff)
{
    extern __shared__ char smem[];
    const uint32_t sb = smem_u32(smem);
    const int tid = threadIdx.x;
    const int lane = tid & 31, wid = tid >> 5;
    const int wr0 = (wid & 7) * 32;   // warp row offset within 256
    const int wc0 = (wid >> 3) * 64;  // warp col offset within 128

    int bid = blockIdx.x;
    if (bid >= ntile0) {
        bid -= ntile0;
        if (INH) A = (const float*)((const __half*)A + aOff);
        else     A += aOff;
        kin = kinB;
        blob += blobOff;
        bias += biasOff;
        c0 += OUTH ? (ptrdiff_t)(cOff / 2) : (ptrdiff_t)cOff;
        if (c1) c1 += OUTH ? (ptrdiff_t)(cOff / 2) : (ptrdiff_t)cOff;
        if (c2) c2 += OUTH ? (ptrdiff_t)(cOff / 2) : (ptrdiff_t)cOff;
        if (MODE == 3) {
            xold = (const float*)((const __half*)xold + cOff);  // xold is fp16
            skipp += skipOff;
        }
    }
    const int row0 = bid * 256;

    // prefetch B image pair for m=0 into buf0 (overlaps with A load/convert below)
    {
        const char* src = (const char*)blob;
        for (int i = tid; i < 4352; i += 512)
            CP_ASYNC16(sb + SM_B0 + i * 16, src + i * 16);
        CP_COMMIT();
    }

    // ---- load A tile 256 x 128 -> fp16 into smem ----
#pragma unroll
    for (int it = 0; it < 8; ++it) {
        int gid = it * 512 + tid;
        int r = gid >> 4;
        int c8 = (gid & 15) * 8;
        float f[8];
        int grow = row0 + r;
        if (grow < nrows && c8 < kin) {
            if (INH) {
                const __half* Ah = (const __half*)A;
                uint4 raw = *reinterpret_cast<const uint4*>(Ah + (size_t)grow * kin + c8);
                const __half2* hp = reinterpret_cast<const __half2*>(&raw);
#pragma unroll
                for (int j = 0; j < 4; ++j) {
                    float2 fv = __half22float2(hp[j]);
                    f[2 * j] = fv.x; f[2 * j + 1] = fv.y;
                }
            } else {
                const float4* p = reinterpret_cast<const float4*>(A + (size_t)grow * kin + c8);
                float4 v0 = p[0], v1 = p[1];
                f[0] = v0.x; f[1] = v0.y; f[2] = v0.z; f[3] = v0.w;
                f[4] = v1.x; f[5] = v1.y; f[6] = v1.z; f[7] = v1.w;
            }
        } else {
#pragma unroll
            for (int j = 0; j < 8; ++j) f[j] = 0.f;
        }
        if (MODE == 3) {
#pragma unroll
            for (int j = 0; j < 8; ++j) f[j] = gelu_f(f[j]);
        }
        uint32_t hw[4];
#pragma unroll
        for (int j = 0; j < 4; ++j) {
            __half2 h2 = __floats2half2_rn(f[2 * j], f[2 * j + 1]);
            hw[j] = *reinterpret_cast<uint32_t*>(&h2);
        }
        uint32_t off = (uint32_t)r * ROWB + (uint32_t)c8 * 2;
        *reinterpret_cast<uint4*>(smem + SM_A + off) = make_uint4(hw[0], hw[1], hw[2], hw[3]);
    }

    float alpha = 0.f;
    if (MODE == 3) alpha = 1.f / (1.f + __expf(-skipp[0]));

    // fragment addresses (lane-dependent; buffer base + k-step added in loop)
    const uint32_t aAddrBase = sb + SM_A + (uint32_t)(wr0 + (lane & 15)) * ROWB + (uint32_t)(lane >> 4) * 16;
    const uint32_t bRowN = (uint32_t)(wc0 + (lane & 7) + ((lane >> 4) & 1) * 8);
    const uint32_t bColK = (uint32_t)(((lane >> 3) & 1) * 8);
    const uint32_t bFragOff = bRowN * ROWB + bColK * 2;

    for (int m = 0; m < nmat; ++m) {
        CP_WAIT0();
        __syncthreads();   // B[m] visible to all; also covers A-tile visibility at m=0
        // kick prefetch of next B image pair into the other buffer (overlaps with MMA below)
        if (m + 1 < nmat) {
            const char* src = (const char*)(blob + (size_t)(m + 1) * 4352);
            uint32_t dstb = sb + ((m + 1) & 1 ? SM_B1 : SM_B0);
            for (int i = tid; i < 4352; i += 512)
                CP_ASYNC16(dstb + i * 16, src + i * 16);
            CP_COMMIT();
        }
        const uint32_t bAddrBase = sb + ((m & 1) ? SM_B1 : SM_B0) + bFragOff;

        float acc[2][8][4];
#pragma unroll
        for (int i = 0; i < 2; ++i)
#pragma unroll
            for (int j = 0; j < 8; ++j)
#pragma unroll
                for (int t = 0; t < 4; ++t) acc[i][j][t] = 0.f;

#pragma unroll 1
        for (int ks = 0; ks < 8; ++ks) {
            uint32_t af[2][4];
#pragma unroll
            for (int i = 0; i < 2; ++i) {
                uint32_t ra = aAddrBase + (uint32_t)i * 16 * ROWB + (uint32_t)ks * 32;
                LDM4(af[i][0], af[i][1], af[i][2], af[i][3], ra);
            }
            // 4 groups of 16 cols; B frags short-lived to cap register pressure
#pragma unroll
            for (int jp = 0; jp < 4; ++jp) {
                uint32_t rb = bAddrBase + (uint32_t)jp * 16 * ROWB + (uint32_t)ks * 32;
                uint32_t h0, h1, h2, h3, l0, l1, l2, l3;
                LDM4(h0, h1, h2, h3, rb);
                LDM4(l0, l1, l2, l3, rb + HALFB);
#pragma unroll
                for (int i = 0; i < 2; ++i) {
                    MMA16816(acc[i][2 * jp], af[i], h0, h1);
                    MMA16816(acc[i][2 * jp + 1], af[i], h2, h3);
                    MMA16816(acc[i][2 * jp], af[i], l0, l1);
                    MMA16816(acc[i][2 * jp + 1], af[i], l2, l3);
                }
            }
        }

        // ---- epilogue ----
        float* C = (m == 0) ? c0 : ((m == 1) ? c1 : c2);
#pragma unroll
        for (int i = 0; i < 2; ++i) {
            int rA = row0 + wr0 + i * 16 + (lane >> 2);
            int rB = rA + 8;
#pragma unroll
            for (int j = 0; j < 8; ++j) {
                int c = wc0 + j * 8 + (lane & 3) * 2;
                if (c >= nout) continue;
                float b0 = bias[m * 128 + c];
                float b1 = bias[m * 128 + c + 1];
                if (rA < nrows) {
                    float o0 = acc[i][j][0] + b0;
                    float o1 = acc[i][j][1] + b1;
                    if (MODE == 1) { o0 = fmaxf(o0, 0.f); o1 = fmaxf(o1, 0.f); }
                    if (MODE == 3) {
                        const __half2* xo = reinterpret_cast<const __half2*>(
                            (const __half*)xold + (size_t)rA * 128 + c);
                        float2 xv = __half22float2(*xo);
                        o0 = alpha * o0 + (1.f - alpha) * xv.x;
                        o1 = alpha * o1 + (1.f - alpha) * xv.y;
                    }
                    if (OUTH)
                        *reinterpret_cast<__half2*>(reinterpret_cast<__half*>(C) + (size_t)rA * nout + c) =
                            __floats2half2_rn(o0, o1);
                    else
                        *reinterpret_cast<float2*>(C + (size_t)rA * nout + c) = make_float2(o0, o1);
                }
                if (rB < nrows) {
                    float o0 = acc[i][j][2] + b0;
                    float o1 = acc[i][j][3] + b1;
                    if (MODE == 1) { o0 = fmaxf(o0, 0.f); o1 = fmaxf(o1, 0.f); }
                    if (MODE == 3) {
                        const __half2* xo = reinterpret_cast<const __half2*>(
                            (const __half*)xold + (size_t)rB * 128 + c);
                        float2 xv = __half22float2(*xo);
                        o0 = alpha * o0 + (1.f - alpha) * xv.x;
                        o1 = alpha * o1 + (1.f - alpha) * xv.y;
                    }
                    if (OUTH)
                        *reinterpret_cast<__half2*>(reinterpret_cast<__half*>(C) + (size_t)rB * nout + c) =
                            __floats2half2_rn(o0, o1);
                    else
                        *reinterpret_cast<float2*>(C + (size_t)rB * nout + c) = make_float2(o0, o1);
                }
            }
        }
        __syncthreads();  // WAR: protect buf[(m+1)&1]'s old contents readers before next prefetch
    }
}

// ---------------- CSR build ----------------
__global__ void hist2_kernel(const int* __restrict__ dstA, const int* __restrict__ dstB,
                             int* __restrict__ deg, int E, int eblk)
{
    int b = blockIdx.x;
    const int r = (b >= eblk) ? 1 : 0;
    if (r) b -= eblk;
    const int* dst = r ? dstB : dstA;
    int i = b * 256 + threadIdx.x;
    if (i < E) atomicAdd(&deg[r * NMAX + dst[i]], 1);
}

__global__ void psum_kernel(const int* __restrict__ deg, int* __restrict__ bsum,
                            int n, int nblk)
{
    __shared__ int ws[32];
    const int r = blockIdx.x / nblk;
    const int b = blockIdx.x % nblk;
    const int tid = threadIdx.x;  // 1024
    int i = b * 1024 + tid;
    int v = (i < n) ? deg[r * NMAX + i] : 0;
#pragma unroll
    for (int d = 16; d > 0; d >>= 1) v += __shfl_xor_sync(0xffffffffu, v, d);
    if ((tid & 31) == 0) ws[tid >> 5] = v;
    __syncthreads();
    if (tid < 32) {
        int x = ws[tid];
#pragma unroll
        for (int d = 16; d > 0; d >>= 1) x += __shfl_xor_sync(0xffffffffu, x, d);
        if (tid == 0) bsum[r * 1024 + b] = x;
    }
}

__global__ void bscan_kernel(int* __restrict__ bsum, int nblk)
{
    __shared__ int ws[32];
    const int tid = threadIdx.x;  // 1024
    for (int r = 0; r < 2; ++r) {
        int* a = bsum + r * 1024;
        int v = (tid < nblk) ? a[tid] : 0;
        int x = v;
#pragma unroll
        for (int d = 1; d < 32; d <<= 1) {
            int y = __shfl_up_sync(0xffffffffu, x, d);
            if ((tid & 31) >= d) x += y;
        }
        if ((tid & 31) == 31) ws[tid >> 5] = x;
        __syncthreads();
        if (tid < 32) {
            int w = ws[tid];
#pragma unroll
            for (int d = 1; d < 32; d <<= 1) {
                int y = __shfl_up_sync(0xffffffffu, w, d);
                if (tid >= d) w += y;
            }
            ws[tid] = w;
        }
        __syncthreads();
        int incl = x + ((tid >= 32) ? ws[(tid >> 5) - 1] : 0);
        if (tid < nblk) a[tid] = incl - v;  // exclusive
        __syncthreads();
    }
}

__global__ void blockscan_kernel(const int* __restrict__ deg, const int* __restrict__ bsum,
                                 int* __restrict__ off, int* __restrict__ cur,
                                 int n, int nblk)
{
    __shared__ int ws[32];
    const int r = blockIdx.x / nblk;
    const int b = blockIdx.x % nblk;
    const int tid = threadIdx.x;  // 1024
    const int i = b * 1024 + tid;
    int v = (i < n) ? deg[r * NMAX + i] : 0;
    int x = v;
#pragma unroll
    for (int d = 1; d < 32; d <<= 1) {
        int y = __shfl_up_sync(0xffffffffu, x, d);
        if ((tid & 31) >= d) x += y;
    }
    if ((tid & 31) == 31) ws[tid >> 5] = x;
    __syncthreads();
    if (tid < 32) {
        int w = ws[tid];
#pragma unroll
        for (int d = 1; d < 32; d <<= 1) {
            int y = __shfl_up_sync(0xffffffffu, w, d);
            if (tid >= d) w += y;
        }
        ws[tid] = w;
    }
    __syncthreads();
    int incl = x + ((tid >= 32) ? ws[(tid >> 5) - 1] : 0) + bsum[r * 1024 + b];
    if (i < n) {
        off[r * (NMAX + 1) + i + 1] = incl;
        cur[r * NMAX + i] = incl - v;  // == off[i] (exclusive prefix)
    }
    if (b == 0 && tid == 0) off[r * (NMAX + 1)] = 0;
}

__global__ void fill2_kernel(const int* __restrict__ eA, const int* __restrict__ eB,
                             int* __restrict__ cur, int* __restrict__ csrc, int E, int eblk)
{
    int b = blockIdx.x;
    const int r = (b >= eblk) ? 1 : 0;
    if (r) b -= eblk;
    const int* ep = r ? eB : eA;
    int i = b * 256 + threadIdx.x;
    if (i < E) {
        int p = atomicAdd(&cur[r * NMAX + ep[E + i]], 1);
        csrc[r * EMAX + p] = ep[i];
    }
}

// ---------------- flash attention: warp per dst node, single relation per launch ----------------
__device__ __forceinline__ float4 ldh4(const __half* p) {
    uint2 raw = *reinterpret_cast<const uint2*>(p);
    __half2 h0 = *reinterpret_cast<const __half2*>(&raw.x);
    __half2 h1 = *reinterpret_cast<const __half2*>(&raw.y);
    float2 a = __half22float2(h0), b = __half22float2(h1);
    return make_float4(a.x, a.y, b.x, b.y);
}

__global__ void attn_fused(const int* __restrict__ offr, const int* __restrict__ csr,
                           const __half* __restrict__ q, const __half* __restrict__ kr,
                           const __half* __restrict__ vr,
                           __half* __restrict__ out, int n)
{
    int w = (blockIdx.x * blockDim.x + threadIdx.x) >> 5;
    int lane = threadIdx.x & 31;
    if (w >= n) return;

    const int beg = offr[w], end = offr[w + 1];
    float4 q4 = ldh4(q + (size_t)w * HIDC + lane * 4);

    float m = -INFINITY, ss = 0.f;
    float4 acc = make_float4(0.f, 0.f, 0.f, 0.f);
    int i = beg;
    // 2-way unrolled online softmax: 4 independent gathers in flight per step
    for (; i + 2 <= end; i += 2) {
        int s0 = csr[i], s1 = csr[i + 1];
        float4 k0 = ldh4(kr + (size_t)s0 * HIDC + lane * 4);
        float4 v0 = ldh4(vr + (size_t)s0 * HIDC + lane * 4);
        float4 k1 = ldh4(kr + (size_t)s1 * HIDC + lane * 4);
        float4 v1 = ldh4(vr + (size_t)s1 * HIDC + lane * 4);
        float p0 = q4.x * k0.x + q4.y * k0.y + q4.z * k0.z + q4.w * k0.w;
        float p1 = q4.x * k1.x + q4.y * k1.y + q4.z * k1.z + q4.w * k1.w;
        p0 += __shfl_xor_sync(0xffffffffu, p0, 1);
        p1 += __shfl_xor_sync(0xffffffffu, p1, 1);
        p0 += __shfl_xor_sync(0xffffffffu, p0, 2);
        p1 += __shfl_xor_sync(0xffffffffu, p1, 2);
        float mn = fmaxf(m, fmaxf(p0, p1));
        float corr = __expf(m - mn);
        float w0 = __expf(p0 - mn);
        float w1 = __expf(p1 - mn);
        ss = ss * corr + w0 + w1;
        acc.x = acc.x * corr + w0 * v0.x + w1 * v1.x;
        acc.y = acc.y * corr + w0 * v0.y + w1 * v1.y;
        acc.z = acc.z * corr + w0 * v0.z + w1 * v1.z;
        acc.w = acc.w * corr + w0 * v0.w + w1 * v1.w;
        m = mn;
    }
    if (i < end) {
        int s = csr[i];
        float4 k4 = ldh4(kr + (size_t)s * HIDC + lane * 4);
        float4 v4 = ldh4(vr + (size_t)s * HIDC + lane * 4);
        float p = q4.x * k4.x + q4.y * k4.y + q4.z * k4.z + q4.w * k4.w;
        p += __shfl_xor_sync(0xffffffffu, p, 1);
        p += __shfl_xor_sync(0xffffffffu, p, 2);
        float mn = fmaxf(m, p);
        float corr = __expf(m - mn);
        float wgt = __expf(p - mn);
        ss = ss * corr + wgt;
        acc.x = acc.x * corr + wgt * v4.x;
        acc.y = acc.y * corr + wgt * v4.y;
        acc.z = acc.z * corr + wgt * v4.z;
        acc.w = acc.w * corr + wgt * v4.w;
        m = mn;
    }
    const float is = 1.f / (ss + 1e-16f);
    __half2 o0 = __floats2half2_rn(acc.x * is, acc.y * is);
    __half2 o1 = __floats2half2_rn(acc.z * is, acc.w * is);
    uint2 packed;
    packed.x = *reinterpret_cast<uint32_t*>(&o0);
    packed.y = *reinterpret_cast<uint32_t*>(&o1);
    *reinterpret_cast<uint2*>(out + (size_t)w * HIDC + lane * 4) = packed;
}

// ---------------- launch ----------------
extern "C" void kernel_launch(void* const* d_in, const int* in_sizes, int n_in,
                              void* d_out, int out_size)
{
    const float* x_cpd    = (const float*)d_in[0];
    const float* x_ko     = (const float*)d_in[1];
    const int*   e_c2k    = (const int*)d_in[2];
    const int*   e_k2c    = (const int*)d_in[3];
    const float* w_in_cpd = (const float*)d_in[4];
    const float* b_in_cpd = (const float*)d_in[5];
    const float* w_in_ko  = (const float*)d_in[6];
    const float* b_in_ko  = (const float*)d_in[7];

    const float *w_k, *b_k, *w_q, *b_q, *w_v, *b_v;
    const float *a_rel, *m_rel, *p_rel, *w_a, *b_a, *skip, *w_out, *b_out;
    if (in_sizes[9] == 2 * 2 * HIDC) {
        w_k = (const float*)d_in[8];   b_k = (const float*)d_in[9];
        w_q = (const float*)d_in[10];  b_q = (const float*)d_in[11];
        w_v = (const float*)d_in[12];  b_v = (const float*)d_in[13];
        a_rel = (const float*)d_in[14]; m_rel = (const float*)d_in[15];
        p_rel = (const float*)d_in[16];
        w_a = (const float*)d_in[17];  b_a = (const float*)d_in[18];
        skip = (const float*)d_in[19];
        w_out = (const float*)d_in[20]; b_out = (const float*)d_in[21];
    } else {
        w_k = (const float*)d_in[8];   w_q = (const float*)d_in[9];
        w_v = (const float*)d_in[10];  w_a = (const float*)d_in[11];
        b_k = (const float*)d_in[12];  b_q = (const float*)d_in[13];
        b_v = (const float*)d_in[14];  b_a = (const float*)d_in[15];
        a_rel = (const float*)d_in[16]; m_rel = (const float*)d_in[17];
        p_rel = (const float*)d_in[18]; skip = (const float*)d_in[19];
        w_out = (const float*)d_in[20]; b_out = (const float*)d_in[21];
    }

    const int N = in_sizes[0] / 64;
    const int E = in_sizes[2] / 2;

    void* p;
    __half *xA, *xB, *qh, *kh, *vh, *att;
    int *deg, *off, *cur, *csrc, *bsum;
    uint4* wblob;
    float* biasP;
    cudaGetSymbolAddress(&p, g_xA);  xA  = (__half*)p;
    cudaGetSymbolAddress(&p, g_xB);  xB  = (__half*)p;
    cudaGetSymbolAddress(&p, g_qh);  qh  = (__half*)p;
    cudaGetSymbolAddress(&p, g_kh);  kh  = (__half*)p;
    cudaGetSymbolAddress(&p, g_vh);  vh  = (__half*)p;
    cudaGetSymbolAddress(&p, g_att); att = (__half*)p;
    cudaGetSymbolAddress(&p, g_deg); deg = (int*)p;
    cudaGetSymbolAddress(&p, g_off); off = (int*)p;
    cudaGetSymbolAddress(&p, g_cur); cur = (int*)p;
    cudaGetSymbolAddress(&p, g_csrc); csrc = (int*)p;
    cudaGetSymbolAddress(&p, g_bsum); bsum = (int*)p;
    cudaGetSymbolAddress(&p, g_wblob); wblob = (uint4*)p;
    cudaGetSymbolAddress(&p, g_biasP); biasP = (float*)p;

    const size_t NSTR = (size_t)NMAX * HIDC;

    // ---- weight prep jobs ----
    PrepArgs pa;
    auto setjob = [&](int idx, const float* W, const float* b, const float* rel,
                      const float* psc, int kin, int nout) {
        pa.j[idx].W = W; pa.j[idx].b = b; pa.j[idx].rel = rel; pa.j[idx].psc = psc;
        pa.j[idx].kin = kin; pa.j[idx].nout = nout;
        pa.j[idx].blob = wblob + (size_t)idx * 4352;
        pa.j[idx].bias = biasP + (size_t)idx * 128;
    };
    setjob(0, w_in_cpd, b_in_cpd, nullptr, nullptr, 64, 128);
    setjob(1, w_in_ko,  b_in_ko,  nullptr, nullptr, 128, 128);
    for (int l = 0; l < 2; ++l)
        for (int t = 0; t < 2; ++t) {
            int lt = l * 2 + t;
            int base = 2 + lt * 4;
            setjob(base + 0, w_q + (size_t)lt * HIDC * HIDC, b_q + (size_t)lt * HIDC,
                   nullptr, p_rel + (size_t)(l * 2 + (1 - t)) * NH, 128, 128);
            setjob(base + 1, w_k + (size_t)lt * HIDC * HIDC, b_k + (size_t)lt * HIDC,
                   a_rel + (size_t)lt * NH * HD * HD, nullptr, 128, 128);
            setjob(base + 2, w_v + (size_t)lt * HIDC * HIDC, b_v + (size_t)lt * HIDC,
                   m_rel + (size_t)lt * NH * HD * HD, nullptr, 128, 128);
            setjob(base + 3, w_a + (size_t)lt * HIDC * HIDC, b_a + (size_t)lt * HIDC,
                   nullptr, nullptr, 128, 128);
        }
    setjob(18, w_out, b_out, nullptr, nullptr, 128, 64);

    cudaFuncSetAttribute(gemm_hmma<0, 0, 1>, cudaFuncAttributeMaxDynamicSharedMemorySize, SMEM_TOT);
    cudaFuncSetAttribute(gemm_hmma<0, 1, 1>, cudaFuncAttributeMaxDynamicSharedMemorySize, SMEM_TOT);
    cudaFuncSetAttribute(gemm_hmma<1, 1, 0>, cudaFuncAttributeMaxDynamicSharedMemorySize, SMEM_TOT);
    cudaFuncSetAttribute(gemm_hmma<3, 1, 1>, cudaFuncAttributeMaxDynamicSharedMemorySize, SMEM_TOT);

    const int gB = (N + 255) / 256;   // 256-row tiles
    const int eblk = (E + 255) / 256;
    const int awgrid = (N + 7) / 8;   // flash attention, warp per node, one relation per launch
    const int nblk = (N + 1023) / 1024;

    __half* xcur = xA;
    __half* xnxt = xB;

    auto launch_qkv = [&](int l, __half* xc) {
        int b0 = 2 + (l * 2) * 4;
        gemm_hmma<0, 1, 1><<<2 * gB, 512, SMEM_TOT>>>(
            (const float*)xc, 128, wblob + (size_t)b0 * 4352, biasP + (size_t)b0 * 128, 3, 128,
            (float*)qh, (float*)kh, (float*)vh, N, nullptr, nullptr,
            gB, 128, (ptrdiff_t)NSTR, (size_t)4 * 4352, 4 * 128, NSTR, 0);
    };

    prep_kernel<<<19, 256>>>(pa);
    gemm_hmma<1, 1, 0><<<2 * gB, 512, SMEM_TOT>>>(
        x_cpd, 64, wblob, biasP, 1, 128,
        (float*)xA, nullptr, nullptr, N, nullptr, nullptr,
        gB, 128, (ptrdiff_t)(x_ko - x_cpd), 4352, 128, NSTR, 0);
    cudaMemsetAsync(deg, 0, sizeof(int) * 2 * NMAX);
    hist2_kernel<<<2 * eblk, 256>>>(e_c2k + E, e_k2c + E, deg, E, eblk);
    launch_qkv(0, xcur);
    psum_kernel<<<2 * nblk, 1024>>>(deg, bsum, N, nblk);
    bscan_kernel<<<1, 1024>>>(bsum, nblk);
    blockscan_kernel<<<2 * nblk, 1024>>>(deg, bsum, off, cur, N, nblk);
    fill2_kernel<<<2 * eblk, 256>>>(e_c2k, e_k2c, cur, csrc, E, eblk);

    for (int l = 0; l < 2; ++l) {
        if (l > 0) launch_qkv(l, xcur);
        // relation 0: src type 0 -> dst type 1 ; relation 1: src type 1 -> dst type 0
        attn_fused<<<awgrid, 256>>>(off, csrc, qh + NSTR, kh, vh, att + NSTR, N);
        attn_fused<<<awgrid, 256>>>(off + (NMAX + 1), csrc + EMAX, qh, kh + NSTR, vh + NSTR, att, N);
        {
            int b0 = 2 + (l * 2) * 4 + 3;
            gemm_hmma<3, 1, 1><<<2 * gB, 512, SMEM_TOT>>>(
                (const float*)att, 128, wblob + (size_t)b0 * 4352, biasP + (size_t)b0 * 128, 1, 128,
                (float*)xnxt, nullptr, nullptr, N, (const float*)xcur, skip + l * 2,
                gB, 128, (ptrdiff_t)NSTR, (size_t)4 * 4352, 4 * 128, NSTR, 1);
        }
        __half* tmp = xcur; xcur = xnxt; xnxt = tmp;
    }

    // final output projection: x[0] and x[1] are contiguous in the ping-pong buffer (fp16 in, fp32 out)
    float* out = (float*)d_out;
    const int gB2 = (2 * N + 255) / 256;
    gemm_hmma<0, 0, 1><<<gB2, 512, SMEM_TOT>>>(
        (const float*)xcur, 128, wblob + (size_t)18 * 4352, biasP + (size_t)18 * 128, 1, 64,
        out, nullptr, nullptr, 2 * N, nullptr, nullptr,
        gB2, 128, 0, 0, 0, 0, 0);
}

// round 16
// speedup vs baseline: 1.0250x; 1.0250x over previous
#include <cuda_runtime.h>
#include <cuda_bf16.h>
#include <cuda_fp16.h>
#include <math.h>
#include <stdint.h>
#include <stddef.h>

#define NMAX 200000
#define EMAX 600000
#define HIDC 128
#define NH 8
#define HD 16

// A/B smem tile: 128 rows x 136 fp16 (272 bytes per row; +16B pad -> conflict-free ldmatrix)
#define ROWB 272
#define HALFB 34816        // 128 * 272 (one image)
#define SM_A  0
#define SM_B0 34816
#define SM_B1 104448
#define SMEM_TOT 174080

// ---------------- scratch (device globals; no runtime allocation) ----------------
__device__ __half g_xA[2][(size_t)NMAX * HIDC];
__device__ __half g_xB[2][(size_t)NMAX * HIDC];
__device__ __half g_qh[2][(size_t)NMAX * HIDC];
__device__ __half g_kh[2][(size_t)NMAX * HIDC];
__device__ __half g_vh[2][(size_t)NMAX * HIDC];
__device__ __half g_att[2][(size_t)NMAX * HIDC];
// CSR (built once per launch; edges constant across layers)
__device__ int g_deg[2][NMAX];
__device__ int g_off[2][NMAX + 1];
__device__ int g_cur[2][NMAX];
__device__ int g_csrc[2][EMAX];
__device__ int g_bsum[2][1024];
// prepped weights: 19 matrices, each 69632 B (fp16 hi image 34816 + fp16 lo image 34816)
__device__ uint4 g_wblob[19][4352];
__device__ float g_biasP[19][128];

// ---------------- helpers ----------------
__device__ __forceinline__ uint32_t smem_u32(const void* p) {
    uint32_t a;
    asm("{ .reg .u64 t; cvta.to.shared.u64 t, %1; cvt.u32.u64 %0, t; }" : "=r"(a) : "l"(p));
    return a;
}

#define LDM4(r0, r1, r2, r3, addr) \
    asm volatile("ldmatrix.sync.aligned.m8n8.x4.shared.b16 {%0,%1,%2,%3}, [%4];" \
                 : "=r"(r0), "=r"(r1), "=r"(r2), "=r"(r3) : "r"(addr))

#define MMA16816(c, a, b) \
    asm volatile("mma.sync.aligned.m16n8k16.row.col.f32.f16.f16.f32 " \
                 "{%0,%1,%2,%3},{%4,%5,%6,%7},{%8,%9},{%0,%1,%2,%3};" \
                 : "+f"((c)[0]), "+f"((c)[1]), "+f"((c)[2]), "+f"((c)[3]) \
                 : "r"((a)[0]), "r"((a)[1]), "r"((a)[2]), "r"((a)[3]), \
                   "r"((b)[0]), "r"((b)[1]))

#define CP_ASYNC16(dst, src) \
    asm volatile("cp.async.cg.shared.global [%0], [%1], 16;" :: "r"(dst), "l"(src))
#define CP_COMMIT() asm volatile("cp.async.commit_group;" ::: "memory")
#define CP_WAIT0()  asm volatile("cp.async.wait_group 0;" ::: "memory")

__device__ __forceinline__ float gelu_f(float x) {
    return 0.5f * x * (1.0f + erff(x * 0.7071067811865475f));
}

// ---------------- weight prep: compose rel/p-scale, transpose to [n][k], fp16 hi/lo split ----------------
struct PrepJob {
    const float* W;    // [kin x nout] row-major
    const float* b;    // [nout]
    const float* rel;  // [8,16,16] or null
    const float* psc;  // [8] or null (also multiplies 0.25 = 1/sqrt(D))
    int kin;
    int nout;
    uint4* blob;
    float* bias;
};
struct PrepArgs { PrepJob j[19]; };

__global__ void prep_kernel(PrepArgs pa) {
    __shared__ float rel_s[2048];
    __shared__ float bsrc[128];
    const PrepJob jb = pa.j[blockIdx.x];
    const int tid = threadIdx.x;
    const bool hasrel = (jb.rel != nullptr);
    if (hasrel)
        for (int i = tid; i < 2048; i += 256) rel_s[i] = jb.rel[i];
    for (int i = tid; i < 128; i += 256) bsrc[i] = (i < jb.nout) ? jb.b[i] : 0.f;
    __syncthreads();

    char* blob = (char*)jb.blob;
    for (int i = tid; i < 16384; i += 256) {
        int k = i >> 7;
        int n = i & 127;
        float v = 0.f;
        if (k < jb.kin && n < jb.nout) {
            if (hasrel) {
                int h = n >> 4, e = n & 15;
                const float* wrow = jb.W + (size_t)k * 128 + h * 16;
                const float* rr = rel_s + h * 256 + e;
                float s = 0.f;
#pragma unroll
                for (int d = 0; d < 16; ++d) s = fmaf(wrow[d], rr[d * 16], s);
                v = s;
            } else {
                v = jb.W[(size_t)k * jb.nout + n];
            }
            if (jb.psc) v *= jb.psc[n >> 4] * 0.25f;
        }
        __half hi = __float2half(v);
        __half lo = __float2half(v - __half2float(hi));
        uint32_t off = (uint32_t)n * ROWB + (uint32_t)k * 2;  // B stored [n][k]
        *reinterpret_cast<__half*>(blob + off) = hi;
        *reinterpret_cast<__half*>(blob + HALFB + off) = lo;
    }
    if (tid < 128) {
        int n = tid;
        float bc;
        if (hasrel) {
            int h = n >> 4, e = n & 15;
            float s = 0.f;
#pragma unroll
            for (int d = 0; d < 16; ++d) s = fmaf(bsrc[h * 16 + d], rel_s[h * 256 + d * 16 + e], s);
            bc = s;
        } else {
            bc = bsrc[n];
        }
        if (jb.psc) bc *= jb.psc[n >> 4] * 0.25f;
        jb.bias[n] = bc;
    }
}

// ---------------- fp16 A x fp16(hi/lo) B HMMA GEMM (512 threads, cp.async double-buffered B) ----------------
// 128x128 CTA tile, 16 warps in 4x4 grid (warp tile 32x32). Two problem halves per grid.
// MODE: 0 plain, 1 relu, 3 pre-gelu on A + sigmoid-skip blend with fp16 xold
// OUTH: 1 -> fp16 outputs; INH: 1 -> A is fp16 (aOff counted in halves)
template <int MODE, int OUTH, int INH>
__global__ void __launch_bounds__(512, 1)
gemm_hmma(const float* A, int kin,
          const uint4* blob, const float* bias,
          int nmat, int nout,
          float* c0, float* c1, float* c2,
          int nrows, const float* xold, const float* skipp,
          int ntile0, int kinB, ptrdiff_t aOff, size_t blobOff, int biasOff,
          size_t cOff, int skipOff)
{
    extern __shared__ char smem[];
    const uint32_t sb = smem_u32(smem);
    const int tid = threadIdx.x;
    const int lane = tid & 31, wid = tid >> 5;
    const int wr0 = (wid & 3) * 32;   // warp row offset within 128
    const int wc0 = (wid >> 2) * 32;  // warp col offset within 128

    int bid = blockIdx.x;
    if (bid >= ntile0) {
        bid -= ntile0;
        if (INH) A = (const float*)((const __half*)A + aOff);
        else     A += aOff;
        kin = kinB;
        blob += blobOff;
        bias += biasOff;
        c0 += OUTH ? (ptrdiff_t)(cOff / 2) : (ptrdiff_t)cOff;
        if (c1) c1 += OUTH ? (ptrdiff_t)(cOff / 2) : (ptrdiff_t)cOff;
        if (c2) c2 += OUTH ? (ptrdiff_t)(cOff / 2) : (ptrdiff_t)cOff;
        if (MODE == 3) {
            xold = (const float*)((const __half*)xold + cOff);  // xold is fp16
            skipp += skipOff;
        }
    }
    const int row0 = bid * 128;

    // prefetch B image pair for m=0 into buf0 (overlaps with A load/convert below)
    {
        const char* src = (const char*)blob;
        for (int i = tid; i < 4352; i += 512)
            CP_ASYNC16(sb + SM_B0 + i * 16, src + i * 16);
        CP_COMMIT();
    }

    // ---- load A tile 128 x 128 -> fp16 into smem ----
#pragma unroll
    for (int it = 0; it < 4; ++it) {
        int gid = it * 512 + tid;
        int r = gid >> 4;
        int c8 = (gid & 15) * 8;
        float f[8];
        int grow = row0 + r;
        if (grow < nrows && c8 < kin) {
            if (INH) {
                const __half* Ah = (const __half*)A;
                uint4 raw = *reinterpret_cast<const uint4*>(Ah + (size_t)grow * kin + c8);
                const __half2* hp = reinterpret_cast<const __half2*>(&raw);
#pragma unroll
                for (int j = 0; j < 4; ++j) {
                    float2 fv = __half22float2(hp[j]);
                    f[2 * j] = fv.x; f[2 * j + 1] = fv.y;
                }
            } else {
                const float4* p = reinterpret_cast<const float4*>(A + (size_t)grow * kin + c8);
                float4 v0 = p[0], v1 = p[1];
                f[0] = v0.x; f[1] = v0.y; f[2] = v0.z; f[3] = v0.w;
                f[4] = v1.x; f[5] = v1.y; f[6] = v1.z; f[7] = v1.w;
            }
        } else {
#pragma unroll
            for (int j = 0; j < 8; ++j) f[j] = 0.f;
        }
        if (MODE == 3) {
#pragma unroll
            for (int j = 0; j < 8; ++j) f[j] = gelu_f(f[j]);
        }
        uint32_t hw[4];
#pragma unroll
        for (int j = 0; j < 4; ++j) {
            __half2 h2 = __floats2half2_rn(f[2 * j], f[2 * j + 1]);
            hw[j] = *reinterpret_cast<uint32_t*>(&h2);
        }
        uint32_t off = (uint32_t)r * ROWB + (uint32_t)c8 * 2;
        *reinterpret_cast<uint4*>(smem + SM_A + off) = make_uint4(hw[0], hw[1], hw[2], hw[3]);
    }

    float alpha = 0.f;
    if (MODE == 3) alpha = 1.f / (1.f + __expf(-skipp[0]));

    // fragment addresses (lane-dependent; buffer base + k-step added in loop)
    const uint32_t aAddrBase = sb + SM_A + (uint32_t)(wr0 + (lane & 15)) * ROWB + (uint32_t)(lane >> 4) * 16;
    const uint32_t bRowN = (uint32_t)(wc0 + (lane & 7) + ((lane >> 4) & 1) * 8);
    const uint32_t bColK = (uint32_t)(((lane >> 3) & 1) * 8);
    const uint32_t bFragOff = bRowN * ROWB + bColK * 2;

    for (int m = 0; m < nmat; ++m) {
        CP_WAIT0();
        __syncthreads();   // B[m] visible to all; also covers A-tile visibility at m=0
        // kick prefetch of next B image pair into the other buffer (overlaps with MMA below)
        if (m + 1 < nmat) {
            const char* src = (const char*)(blob + (size_t)(m + 1) * 4352);
            uint32_t dstb = sb + ((m + 1) & 1 ? SM_B1 : SM_B0);
            for (int i = tid; i < 4352; i += 512)
                CP_ASYNC16(dstb + i * 16, src + i * 16);
            CP_COMMIT();
        }
        const uint32_t bAddrBase = sb + ((m & 1) ? SM_B1 : SM_B0) + bFragOff;

        float acc[2][4][4];
#pragma unroll
        for (int i = 0; i < 2; ++i)
#pragma unroll
            for (int j = 0; j < 4; ++j)
#pragma unroll
                for (int t = 0; t < 4; ++t) acc[i][j][t] = 0.f;

#pragma unroll 2
        for (int ks = 0; ks < 8; ++ks) {
            uint32_t af[2][4];
#pragma unroll
            for (int i = 0; i < 2; ++i) {
                uint32_t ra = aAddrBase + (uint32_t)i * 16 * ROWB + (uint32_t)ks * 32;
                LDM4(af[i][0], af[i][1], af[i][2], af[i][3], ra);
            }
            uint32_t bhi[4][2], blo[4][2];
#pragma unroll
            for (int jp = 0; jp < 2; ++jp) {
                uint32_t rb = bAddrBase + (uint32_t)jp * 16 * ROWB + (uint32_t)ks * 32;
                uint32_t r0, r1, r2, r3;
                LDM4(r0, r1, r2, r3, rb);
                bhi[2 * jp][0] = r0; bhi[2 * jp][1] = r1;
                bhi[2 * jp + 1][0] = r2; bhi[2 * jp + 1][1] = r3;
                LDM4(r0, r1, r2, r3, rb + HALFB);
                blo[2 * jp][0] = r0; blo[2 * jp][1] = r1;
                blo[2 * jp + 1][0] = r2; blo[2 * jp + 1][1] = r3;
            }
#pragma unroll
            for (int i = 0; i < 2; ++i)
#pragma unroll
                for (int j = 0; j < 4; ++j) {
                    MMA16816(acc[i][j], af[i], bhi[j]);
                    MMA16816(acc[i][j], af[i], blo[j]);
                }
        }

        // ---- epilogue ----
        float* C = (m == 0) ? c0 : ((m == 1) ? c1 : c2);
#pragma unroll
        for (int i = 0; i < 2; ++i) {
            int rA = row0 + wr0 + i * 16 + (lane >> 2);
            int rB = rA + 8;
#pragma unroll
            for (int j = 0; j < 4; ++j) {
                int c = wc0 + j * 8 + (lane & 3) * 2;
                if (c >= nout) continue;
                float b0 = bias[m * 128 + c];
                float b1 = bias[m * 128 + c + 1];
                if (rA < nrows) {
                    float o0 = acc[i][j][0] + b0;
                    float o1 = acc[i][j][1] + b1;
                    if (MODE == 1) { o0 = fmaxf(o0, 0.f); o1 = fmaxf(o1, 0.f); }
                    if (MODE == 3) {
                        const __half2* xo = reinterpret_cast<const __half2*>(
                            (const __half*)xold + (size_t)rA * 128 + c);
                        float2 xv = __half22float2(*xo);
                        o0 = alpha * o0 + (1.f - alpha) * xv.x;
                        o1 = alpha * o1 + (1.f - alpha) * xv.y;
                    }
                    if (OUTH)
                        *reinterpret_cast<__half2*>(reinterpret_cast<__half*>(C) + (size_t)rA * nout + c) =
                            __floats2half2_rn(o0, o1);
                    else
                        *reinterpret_cast<float2*>(C + (size_t)rA * nout + c) = make_float2(o0, o1);
                }
                if (rB < nrows) {
                    float o0 = acc[i][j][2] + b0;
                    float o1 = acc[i][j][3] + b1;
                    if (MODE == 1) { o0 = fmaxf(o0, 0.f); o1 = fmaxf(o1, 0.f); }
                    if (MODE == 3) {
                        const __half2* xo = reinterpret_cast<const __half2*>(
                            (const __half*)xold + (size_t)rB * 128 + c);
                        float2 xv = __half22float2(*xo);
                        o0 = alpha * o0 + (1.f - alpha) * xv.x;
                        o1 = alpha * o1 + (1.f - alpha) * xv.y;
                    }
                    if (OUTH)
                        *reinterpret_cast<__half2*>(reinterpret_cast<__half*>(C) + (size_t)rB * nout + c) =
                            __floats2half2_rn(o0, o1);
                    else
                        *reinterpret_cast<float2*>(C + (size_t)rB * nout + c) = make_float2(o0, o1);
                }
            }
        }
        __syncthreads();  // WAR: protect buf[(m+1)&1]'s old contents readers before next prefetch
    }
}

// ---------------- CSR build ----------------
__global__ void hist2_kernel(const int* __restrict__ dstA, const int* __restrict__ dstB,
                             int* __restrict__ deg, int E, int eblk)
{
    int b = blockIdx.x;
    const int r = (b >= eblk) ? 1 : 0;
    if (r) b -= eblk;
    const int* dst = r ? dstB : dstA;
    int i = b * 256 + threadIdx.x;
    if (i < E) atomicAdd(&deg[r * NMAX + dst[i]], 1);
}

__global__ void psum_kernel(const int* __restrict__ deg, int* __restrict__ bsum,
                            int n, int nblk)
{
    __shared__ int ws[32];
    const int r = blockIdx.x / nblk;
    const int b = blockIdx.x % nblk;
    const int tid = threadIdx.x;  // 1024
    int i = b * 1024 + tid;
    int v = (i < n) ? deg[r * NMAX + i] : 0;
#pragma unroll
    for (int d = 16; d > 0; d >>= 1) v += __shfl_xor_sync(0xffffffffu, v, d);
    if ((tid & 31) == 0) ws[tid >> 5] = v;
    __syncthreads();
    if (tid < 32) {
        int x = ws[tid];
#pragma unroll
        for (int d = 16; d > 0; d >>= 1) x += __shfl_xor_sync(0xffffffffu, x, d);
        if (tid == 0) bsum[r * 1024 + b] = x;
    }
}

__global__ void bscan_kernel(int* __restrict__ bsum, int nblk)
{
    __shared__ int ws[32];
    const int tid = threadIdx.x;  // 1024
    for (int r = 0; r < 2; ++r) {
        int* a = bsum + r * 1024;
        int v = (tid < nblk) ? a[tid] : 0;
        int x = v;
#pragma unroll
        for (int d = 1; d < 32; d <<= 1) {
            int y = __shfl_up_sync(0xffffffffu, x, d);
            if ((tid & 31) >= d) x += y;
        }
        if ((tid & 31) == 31) ws[tid >> 5] = x;
        __syncthreads();
        if (tid < 32) {
            int w = ws[tid];
#pragma unroll
            for (int d = 1; d < 32; d <<= 1) {
                int y = __shfl_up_sync(0xffffffffu, w, d);
                if (tid >= d) w += y;
            }
            ws[tid] = w;
        }
        __syncthreads();
        int incl = x + ((tid >= 32) ? ws[(tid >> 5) - 1] : 0);
        if (tid < nblk) a[tid] = incl - v;  // exclusive
        __syncthreads();
    }
}

__global__ void blockscan_kernel(const int* __restrict__ deg, const int* __restrict__ bsum,
                                 int* __restrict__ off, int* __restrict__ cur,
                                 int n, int nblk)
{
    __shared__ int ws[32];
    const int r = blockIdx.x / nblk;
    const int b = blockIdx.x % nblk;
    const int tid = threadIdx.x;  // 1024
    const int i = b * 1024 + tid;
    int v = (i < n) ? deg[r * NMAX + i] : 0;
    int x = v;
#pragma unroll
    for (int d = 1; d < 32; d <<= 1) {
        int y = __shfl_up_sync(0xffffffffu, x, d);
        if ((tid & 31) >= d) x += y;
    }
    if ((tid & 31) == 31) ws[tid >> 5] = x;
    __syncthreads();
    if (tid < 32) {
        int w = ws[tid];
#pragma unroll
        for (int d = 1; d < 32; d <<= 1) {
            int y = __shfl_up_sync(0xffffffffu, w, d);
            if (tid >= d) w += y;
        }
        ws[tid] = w;
    }
    __syncthreads();
    int incl = x + ((tid >= 32) ? ws[(tid >> 5) - 1] : 0) + bsum[r * 1024 + b];
    if (i < n) {
        off[r * (NMAX + 1) + i + 1] = incl;
        cur[r * NMAX + i] = incl - v;  // == off[i] (exclusive prefix)
    }
    if (b == 0 && tid == 0) off[r * (NMAX + 1)] = 0;
}

__global__ void fill2_kernel(const int* __restrict__ eA, const int* __restrict__ eB,
                             int* __restrict__ cur, int* __restrict__ csrc, int E, int eblk)
{
    int b = blockIdx.x;
    const int r = (b >= eblk) ? 1 : 0;
    if (r) b -= eblk;
    const int* ep = r ? eB : eA;
    int i = b * 256 + threadIdx.x;
    if (i < E) {
        int p = atomicAdd(&cur[r * NMAX + ep[E + i]], 1);
        csrc[r * EMAX + p] = ep[i];
    }
}

// ---------------- flash attention: warp per dst node, single relation per launch ----------------
__device__ __forceinline__ float4 ldh4(const __half* p) {
    uint2 raw = *reinterpret_cast<const uint2*>(p);
    __half2 h0 = *reinterpret_cast<const __half2*>(&raw.x);
    __half2 h1 = *reinterpret_cast<const __half2*>(&raw.y);
    float2 a = __half22float2(h0), b = __half22float2(h1);
    return make_float4(a.x, a.y, b.x, b.y);
}

__global__ void attn_fused(const int* __restrict__ offr, const int* __restrict__ csr,
                           const __half* __restrict__ q, const __half* __restrict__ kr,
                           const __half* __restrict__ vr,
                           __half* __restrict__ out, int n)
{
    int w = (blockIdx.x * blockDim.x + threadIdx.x) >> 5;
    int lane = threadIdx.x & 31;
    if (w >= n) return;

    const int beg = offr[w], end = offr[w + 1];
    float4 q4 = ldh4(q + (size_t)w * HIDC + lane * 4);

    float m = -INFINITY, ss = 0.f;
    float4 acc = make_float4(0.f, 0.f, 0.f, 0.f);
    int i = beg;
    // 2-way unrolled online softmax: 4 independent gathers in flight per step
    for (; i + 2 <= end; i += 2) {
        int s0 = csr[i], s1 = csr[i + 1];
        float4 k0 = ldh4(kr + (size_t)s0 * HIDC + lane * 4);
        float4 v0 = ldh4(vr + (size_t)s0 * HIDC + lane * 4);
        float4 k1 = ldh4(kr + (size_t)s1 * HIDC + lane * 4);
        float4 v1 = ldh4(vr + (size_t)s1 * HIDC + lane * 4);
        float p0 = q4.x * k0.x + q4.y * k0.y + q4.z * k0.z + q4.w * k0.w;
        float p1 = q4.x * k1.x + q4.y * k1.y + q4.z * k1.z + q4.w * k1.w;
        p0 += __shfl_xor_sync(0xffffffffu, p0, 1);
        p1 += __shfl_xor_sync(0xffffffffu, p1, 1);
        p0 += __shfl_xor_sync(0xffffffffu, p0, 2);
        p1 += __shfl_xor_sync(0xffffffffu, p1, 2);
        float mn = fmaxf(m, fmaxf(p0, p1));
        float corr = __expf(m - mn);
        float w0 = __expf(p0 - mn);
        float w1 = __expf(p1 - mn);
        ss = ss * corr + w0 + w1;
        acc.x = acc.x * corr + w0 * v0.x + w1 * v1.x;
        acc.y = acc.y * corr + w0 * v0.y + w1 * v1.y;
        acc.z = acc.z * corr + w0 * v0.z + w1 * v1.z;
        acc.w = acc.w * corr + w0 * v0.w + w1 * v1.w;
        m = mn;
    }
    if (i < end) {
        int s = csr[i];
        float4 k4 = ldh4(kr + (size_t)s * HIDC + lane * 4);
        float4 v4 = ldh4(vr + (size_t)s * HIDC + lane * 4);
        float p = q4.x * k4.x + q4.y * k4.y + q4.z * k4.z + q4.w * k4.w;
        p += __shfl_xor_sync(0xffffffffu, p, 1);
        p += __shfl_xor_sync(0xffffffffu, p, 2);
        float mn = fmaxf(m, p);
        float corr = __expf(m - mn);
        float wgt = __expf(p - mn);
        ss = ss * corr + wgt;
        acc.x = acc.x * corr + wgt * v4.x;
        acc.y = acc.y * corr + wgt * v4.y;
        acc.z = acc.z * corr + wgt * v4.z;
        acc.w = acc.w * corr + wgt * v4.w;
        m = mn;
    }
    const float is = 1.f / (ss + 1e-16f);
    __half2 o0 = __floats2half2_rn(acc.x * is, acc.y * is);
    __half2 o1 = __floats2half2_rn(acc.z * is, acc.w * is);
    uint2 packed;
    packed.x = *reinterpret_cast<uint32_t*>(&o0);
    packed.y = *reinterpret_cast<uint32_t*>(&o1);
    *reinterpret_cast<uint2*>(out + (size_t)w * HIDC + lane * 4) = packed;
}

// ---------------- launch ----------------
extern "C" void kernel_launch(void* const* d_in, const int* in_sizes, int n_in,
                              void* d_out, int out_size)
{
    const float* x_cpd    = (const float*)d_in[0];
    const float* x_ko     = (const float*)d_in[1];
    const int*   e_c2k    = (const int*)d_in[2];
    const int*   e_k2c    = (const int*)d_in[3];
    const float* w_in_cpd = (const float*)d_in[4];
    const float* b_in_cpd = (const float*)d_in[5];
    const float* w_in_ko  = (const float*)d_in[6];
    const float* b_in_ko  = (const float*)d_in[7];

    const float *w_k, *b_k, *w_q, *b_q, *w_v, *b_v;
    const float *a_rel, *m_rel, *p_rel, *w_a, *b_a, *skip, *w_out, *b_out;
    if (in_sizes[9] == 2 * 2 * HIDC) {
        w_k = (const float*)d_in[8];   b_k = (const float*)d_in[9];
        w_q = (const float*)d_in[10];  b_q = (const float*)d_in[11];
        w_v = (const float*)d_in[12];  b_v = (const float*)d_in[13];
        a_rel = (const float*)d_in[14]; m_rel = (const float*)d_in[15];
        p_rel = (const float*)d_in[16];
        w_a = (const float*)d_in[17];  b_a = (const float*)d_in[18];
        skip = (const float*)d_in[19];
        w_out = (const float*)d_in[20]; b_out = (const float*)d_in[21];
    } else {
        w_k = (const float*)d_in[8];   w_q = (const float*)d_in[9];
        w_v = (const float*)d_in[10];  w_a = (const float*)d_in[11];
        b_k = (const float*)d_in[12];  b_q = (const float*)d_in[13];
        b_v = (const float*)d_in[14];  b_a = (const float*)d_in[15];
        a_rel = (const float*)d_in[16]; m_rel = (const float*)d_in[17];
        p_rel = (const float*)d_in[18]; skip = (const float*)d_in[19];
        w_out = (const float*)d_in[20]; b_out = (const float*)d_in[21];
    }

    const int N = in_sizes[0] / 64;
    const int E = in_sizes[2] / 2;

    void* p;
    __half *xA, *xB, *qh, *kh, *vh, *att;
    int *deg, *off, *cur, *csrc, *bsum;
    uint4* wblob;
    float* biasP;
    cudaGetSymbolAddress(&p, g_xA);  xA  = (__half*)p;
    cudaGetSymbolAddress(&p, g_xB);  xB  = (__half*)p;
    cudaGetSymbolAddress(&p, g_qh);  qh  = (__half*)p;
    cudaGetSymbolAddress(&p, g_kh);  kh  = (__half*)p;
    cudaGetSymbolAddress(&p, g_vh);  vh  = (__half*)p;
    cudaGetSymbolAddress(&p, g_att); att = (__half*)p;
    cudaGetSymbolAddress(&p, g_deg); deg = (int*)p;
    cudaGetSymbolAddress(&p, g_off); off = (int*)p;
    cudaGetSymbolAddress(&p, g_cur); cur = (int*)p;
    cudaGetSymbolAddress(&p, g_csrc); csrc = (int*)p;
    cudaGetSymbolAddress(&p, g_bsum); bsum = (int*)p;
    cudaGetSymbolAddress(&p, g_wblob); wblob = (uint4*)p;
    cudaGetSymbolAddress(&p, g_biasP); biasP = (float*)p;

    const size_t NSTR = (size_t)NMAX * HIDC;

    // ---- weight prep jobs ----
    PrepArgs pa;
    auto setjob = [&](int idx, const float* W, const float* b, const float* rel,
                      const float* psc, int kin, int nout) {
        pa.j[idx].W = W; pa.j[idx].b = b; pa.j[idx].rel = rel; pa.j[idx].psc = psc;
        pa.j[idx].kin = kin; pa.j[idx].nout = nout;
        pa.j[idx].blob = wblob + (size_t)idx * 4352;
        pa.j[idx].bias = biasP + (size_t)idx * 128;
    };
    setjob(0, w_in_cpd, b_in_cpd, nullptr, nullptr, 64, 128);
    setjob(1, w_in_ko,  b_in_ko,  nullptr, nullptr, 128, 128);
    for (int l = 0; l < 2; ++l)
        for (int t = 0; t < 2; ++t) {
            int lt = l * 2 + t;
            int base = 2 + lt * 4;
            setjob(base + 0, w_q + (size_t)lt * HIDC * HIDC, b_q + (size_t)lt * HIDC,
                   nullptr, p_rel + (size_t)(l * 2 + (1 - t)) * NH, 128, 128);
            setjob(base + 1, w_k + (size_t)lt * HIDC * HIDC, b_k + (size_t)lt * HIDC,
                   a_rel + (size_t)lt * NH * HD * HD, nullptr, 128, 128);
            setjob(base + 2, w_v + (size_t)lt * HIDC * HIDC, b_v + (size_t)lt * HIDC,
                   m_rel + (size_t)lt * NH * HD * HD, nullptr, 128, 128);
            setjob(base + 3, w_a + (size_t)lt * HIDC * HIDC, b_a + (size_t)lt * HIDC,
                   nullptr, nullptr, 128, 128);
        }
    setjob(18, w_out, b_out, nullptr, nullptr, 128, 64);

    cudaFuncSetAttribute(gemm_hmma<0, 0, 1>, cudaFuncAttributeMaxDynamicSharedMemorySize, SMEM_TOT);
    cudaFuncSetAttribute(gemm_hmma<0, 1, 1>, cudaFuncAttributeMaxDynamicSharedMemorySize, SMEM_TOT);
    cudaFuncSetAttribute(gemm_hmma<1, 1, 0>, cudaFuncAttributeMaxDynamicSharedMemorySize, SMEM_TOT);
    cudaFuncSetAttribute(gemm_hmma<3, 1, 1>, cudaFuncAttributeMaxDynamicSharedMemorySize, SMEM_TOT);

    const int gB = (N + 127) / 128;
    const int eblk = (E + 255) / 256;
    const int awgrid = (N + 7) / 8;   // flash attention, warp per node, one relation per launch
    const int nblk = (N + 1023) / 1024;

    __half* xcur = xA;
    __half* xnxt = xB;

    auto launch_qkv = [&](int l, __half* xc) {
        int b0 = 2 + (l * 2) * 4;
        gemm_hmma<0, 1, 1><<<2 * gB, 512, SMEM_TOT>>>(
            (const float*)xc, 128, wblob + (size_t)b0 * 4352, biasP + (size_t)b0 * 128, 3, 128,
            (float*)qh, (float*)kh, (float*)vh, N, nullptr, nullptr,
            gB, 128, (ptrdiff_t)NSTR, (size_t)4 * 4352, 4 * 128, NSTR, 0);
    };

    prep_kernel<<<19, 256>>>(pa);
    gemm_hmma<1, 1, 0><<<2 * gB, 512, SMEM_TOT>>>(
        x_cpd, 64, wblob, biasP, 1, 128,
        (float*)xA, nullptr, nullptr, N, nullptr, nullptr,
        gB, 128, (ptrdiff_t)(x_ko - x_cpd), 4352, 128, NSTR, 0);
    cudaMemsetAsync(deg, 0, sizeof(int) * 2 * NMAX);
    hist2_kernel<<<2 * eblk, 256>>>(e_c2k + E, e_k2c + E, deg, E, eblk);
    launch_qkv(0, xcur);
    psum_kernel<<<2 * nblk, 1024>>>(deg, bsum, N, nblk);
    bscan_kernel<<<1, 1024>>>(bsum, nblk);
    blockscan_kernel<<<2 * nblk, 1024>>>(deg, bsum, off, cur, N, nblk);
    fill2_kernel<<<2 * eblk, 256>>>(e_c2k, e_k2c, cur, csrc, E, eblk);

    for (int l = 0; l < 2; ++l) {
        if (l > 0) launch_qkv(l, xcur);
        // relation 0: src type 0 -> dst type 1 ; relation 1: src type 1 -> dst type 0
        attn_fused<<<awgrid, 256>>>(off, csrc, qh + NSTR, kh, vh, att + NSTR, N);
        attn_fused<<<awgrid, 256>>>(off + (NMAX + 1), csrc + EMAX, qh, kh + NSTR, vh + NSTR, att, N);
        {
            int b0 = 2 + (l * 2) * 4 + 3;
            gemm_hmma<3, 1, 1><<<2 * gB, 512, SMEM_TOT>>>(
                (const float*)att, 128, wblob + (size_t)b0 * 4352, biasP + (size_t)b0 * 128, 1, 128,
                (float*)xnxt, nullptr, nullptr, N, (const float*)xcur, skip + l * 2,
                gB, 128, (ptrdiff_t)NSTR, (size_t)4 * 4352, 4 * 128, NSTR, 1);
        }
        __half* tmp = xcur; xcur = xnxt; xnxt = tmp;
    }

    // final output projection: x[0] and x[1] are contiguous in the ping-pong buffer (fp16 in, fp32 out)
    float* out = (float*)d_out;
    const int gB2 = (2 * N + 127) / 128;
    gemm_hmma<0, 0, 1><<<gB2, 512, SMEM_TOT>>>(
        (const float*)xcur, 128, wblob + (size_t)18 * 4352, biasP + (size_t)18 * 128, 1, 64,
        out, nullptr, nullptr, 2 * N, nullptr, nullptr,
        gB2, 128, 0, 0, 0, 0, 0);
}

// round 17
// speedup vs baseline: 1.0722x; 1.0460x over previous
#include <cuda_runtime.h>
#include <cuda_bf16.h>
#include <cuda_fp16.h>
#include <math.h>
#include <stdint.h>
#include <stddef.h>

#define NMAX 200000
#define EMAX 600000
#define HIDC 128
#define NH 8
#define HD 16

// A/B smem tile: 128 rows x 136 fp16 (272 bytes per row; +16B pad -> conflict-free ldmatrix)
#define ROWB 272
#define HALFB 34816        // 128 * 272 (one image)
#define SM_A  0
#define SM_B0 34816
#define SM_B1 104448
#define SMEM_TOT 174080

// ---------------- scratch (device globals; no runtime allocation) ----------------
__device__ __half g_xA[2][(size_t)NMAX * HIDC];
__device__ __half g_xB[2][(size_t)NMAX * HIDC];
__device__ __half g_qh[2][(size_t)NMAX * HIDC];
__device__ __half g_kh[2][(size_t)NMAX * HIDC];
__device__ __half g_vh[2][(size_t)NMAX * HIDC];
__device__ __half g_att[2][(size_t)NMAX * HIDC];
// CSR (built once per launch; edges constant across layers)
__device__ int g_deg[2][NMAX];
__device__ int g_off[2][NMAX + 1];
__device__ int g_cur[2][NMAX];
__device__ int g_csrc[2][EMAX];
__device__ int g_bsum[2][1024];
// prepped weights: 20 matrices, each 69632 B (fp16 hi image 34816 + fp16 lo image 34816)
__device__ uint4 g_wblob[20][4352];
__device__ float g_biasP[20][128];

// ---------------- helpers ----------------
__device__ __forceinline__ uint32_t smem_u32(const void* p) {
    uint32_t a;
    asm("{ .reg .u64 t; cvta.to.shared.u64 t, %1; cvt.u32.u64 %0, t; }" : "=r"(a) : "l"(p));
    return a;
}

#define LDM4(r0, r1, r2, r3, addr) \
    asm volatile("ldmatrix.sync.aligned.m8n8.x4.shared.b16 {%0,%1,%2,%3}, [%4];" \
                 : "=r"(r0), "=r"(r1), "=r"(r2), "=r"(r3) : "r"(addr))

#define MMA16816(c, a, b) \
    asm volatile("mma.sync.aligned.m16n8k16.row.col.f32.f16.f16.f32 " \
                 "{%0,%1,%2,%3},{%4,%5,%6,%7},{%8,%9},{%0,%1,%2,%3};" \
                 : "+f"((c)[0]), "+f"((c)[1]), "+f"((c)[2]), "+f"((c)[3]) \
                 : "r"((a)[0]), "r"((a)[1]), "r"((a)[2]), "r"((a)[3]), \
                   "r"((b)[0]), "r"((b)[1]))

#define CP_ASYNC16(dst, src) \
    asm volatile("cp.async.cg.shared.global [%0], [%1], 16;" :: "r"(dst), "l"(src))
#define CP_COMMIT() asm volatile("cp.async.commit_group;" ::: "memory")
#define CP_WAIT0()  asm volatile("cp.async.wait_group 0;" ::: "memory")

__device__ __forceinline__ float gelu_f(float x) {
    return 0.5f * x * (1.0f + erff(x * 0.7071067811865475f));
}

// ---------------- weight prep: compose rel/p-scale, transpose to [n][k], fp16 hi/lo split ----------------
struct PrepJob {
    const float* W;    // [kin x nout] row-major
    const float* b;    // [nout]
    const float* rel;  // [8,16,16] or null
    const float* psc;  // [8] or null (also multiplies 0.25 = 1/sqrt(D))
    int kin;
    int nout;
    uint4* blob;
    float* bias;
};
struct PrepArgs { PrepJob j[20]; };

__global__ void prep_kernel(PrepArgs pa) {
    __shared__ float rel_s[2048];
    __shared__ float bsrc[128];
    const PrepJob jb = pa.j[blockIdx.x];
    const int tid = threadIdx.x;
    const bool hasrel = (jb.rel != nullptr);
    if (hasrel)
        for (int i = tid; i < 2048; i += 256) rel_s[i] = jb.rel[i];
    for (int i = tid; i < 128; i += 256) bsrc[i] = (i < jb.nout) ? jb.b[i] : 0.f;
    __syncthreads();

    char* blob = (char*)jb.blob;
    for (int i = tid; i < 16384; i += 256) {
        int k = i >> 7;
        int n = i & 127;
        float v = 0.f;
        if (k < jb.kin && n < jb.nout) {
            if (hasrel) {
                int h = n >> 4, e = n & 15;
                const float* wrow = jb.W + (size_t)k * 128 + h * 16;
                const float* rr = rel_s + h * 256 + e;
                float s = 0.f;
#pragma unroll
                for (int d = 0; d < 16; ++d) s = fmaf(wrow[d], rr[d * 16], s);
                v = s;
            } else {
                v = jb.W[(size_t)k * jb.nout + n];
            }
            if (jb.psc) v *= jb.psc[n >> 4] * 0.25f;
        }
        __half hi = __float2half(v);
        __half lo = __float2half(v - __half2float(hi));
        uint32_t off = (uint32_t)n * ROWB + (uint32_t)k * 2;  // B stored [n][k]
        *reinterpret_cast<__half*>(blob + off) = hi;
        *reinterpret_cast<__half*>(blob + HALFB + off) = lo;
    }
    if (tid < 128) {
        int n = tid;
        float bc;
        if (hasrel) {
            int h = n >> 4, e = n & 15;
            float s = 0.f;
#pragma unroll
            for (int d = 0; d < 16; ++d) s = fmaf(bsrc[h * 16 + d], rel_s[h * 256 + d * 16 + e], s);
            bc = s;
        } else {
            bc = bsrc[n];
        }
        if (jb.psc) bc *= jb.psc[n >> 4] * 0.25f;
        jb.bias[n] = bc;
    }
}

// ---------------- chained HMMA GEMM ----------------
// m=0 computes the activation matrix, writes it to gmem (x) AND into the smem A
// tile; m>=1 are projections off that tile. 128x128 CTA tile, 16 warps (4x4),
// cp.async double-buffered B, two problem halves per grid.
// VARIANT 0: A fp32 (raw inputs), m0 = relu (in-proj), m1..3 = q/k/v (fp16 out)
// VARIANT 1: A fp16 att, gelu on load, m0 = skip-blend, m1..3 = q/k/v
// VARIANT 2: A fp16 att, gelu on load, m0 = skip-blend (smem only), m1 = final fp32 (nout 64)
template <int VARIANT>
__global__ void __launch_bounds__(512, 1)
gemm_chain(const float* A, int kin,
           const uint4* blob, const float* bias,
           __half* c0, __half* c1, __half* c2, __half* c3, float* cf,
           int nrows, const __half* xold, const float* skipp,
           int ntile0, int kinB, ptrdiff_t aOff, size_t blobOff, int biasOff,
           size_t cOff, int skipOff, size_t cfOff)
{
    extern __shared__ char smem[];
    const uint32_t sb = smem_u32(smem);
    const int tid = threadIdx.x;
    const int lane = tid & 31, wid = tid >> 5;
    const int wr0 = (wid & 3) * 32;   // warp row offset within 128
    const int wc0 = (wid >> 2) * 32;  // warp col offset within 128
    const int nmat = (VARIANT == 2) ? 2 : 4;

    int bid = blockIdx.x;
    if (bid >= ntile0) {
        bid -= ntile0;
        if (VARIANT == 0) A += aOff;
        else              A = (const float*)((const __half*)A + aOff);
        kin = kinB;
        blob += blobOff;
        bias += biasOff;
        if (c0) c0 += cOff;
        if (c1) { c1 += cOff; c2 += cOff; c3 += cOff; }
        if (VARIANT == 2) cf += cfOff;
        if (VARIANT != 0) { xold += cOff; skipp += skipOff; }
    }
    const int row0 = bid * 128;

    // prefetch B image pair for m=0 into buf0 (overlaps with A load/convert below)
    {
        const char* src = (const char*)blob;
        for (int i = tid; i < 4352; i += 512)
            CP_ASYNC16(sb + SM_B0 + i * 16, src + i * 16);
        CP_COMMIT();
    }

    // ---- load A tile 128 x 128 -> fp16 into smem ----
#pragma unroll
    for (int it = 0; it < 4; ++it) {
        int gid = it * 512 + tid;
        int r = gid >> 4;
        int c8 = (gid & 15) * 8;
        float f[8];
        int grow = row0 + r;
        if (grow < nrows && c8 < kin) {
            if (VARIANT != 0) {
                const __half* Ah = (const __half*)A;
                uint4 raw = *reinterpret_cast<const uint4*>(Ah + (size_t)grow * kin + c8);
                const __half2* hp = reinterpret_cast<const __half2*>(&raw);
#pragma unroll
                for (int j = 0; j < 4; ++j) {
                    float2 fv = __half22float2(hp[j]);
                    f[2 * j] = fv.x; f[2 * j + 1] = fv.y;
                }
            } else {
                const float4* p = reinterpret_cast<const float4*>(A + (size_t)grow * kin + c8);
                float4 v0 = p[0], v1 = p[1];
                f[0] = v0.x; f[1] = v0.y; f[2] = v0.z; f[3] = v0.w;
                f[4] = v1.x; f[5] = v1.y; f[6] = v1.z; f[7] = v1.w;
            }
        } else {
#pragma unroll
            for (int j = 0; j < 8; ++j) f[j] = 0.f;
        }
        if (VARIANT != 0) {
#pragma unroll
            for (int j = 0; j < 8; ++j) f[j] = gelu_f(f[j]);
        }
        uint32_t hw[4];
#pragma unroll
        for (int j = 0; j < 4; ++j) {
            __half2 h2 = __floats2half2_rn(f[2 * j], f[2 * j + 1]);
            hw[j] = *reinterpret_cast<uint32_t*>(&h2);
        }
        uint32_t off = (uint32_t)r * ROWB + (uint32_t)c8 * 2;
        *reinterpret_cast<uint4*>(smem + SM_A + off) = make_uint4(hw[0], hw[1], hw[2], hw[3]);
    }

    float alpha = 0.f;
    if (VARIANT != 0) alpha = 1.f / (1.f + __expf(-skipp[0]));

    // fragment addresses (lane-dependent; buffer base + k-step added in loop)
    const uint32_t aAddrBase = sb + SM_A + (uint32_t)(wr0 + (lane & 15)) * ROWB + (uint32_t)(lane >> 4) * 16;
    const uint32_t bRowN = (uint32_t)(wc0 + (lane & 7) + ((lane >> 4) & 1) * 8);
    const uint32_t bColK = (uint32_t)(((lane >> 3) & 1) * 8);
    const uint32_t bFragOff = bRowN * ROWB + bColK * 2;

    for (int m = 0; m < nmat; ++m) {
        CP_WAIT0();
        __syncthreads();   // B[m] visible; also A tile (m=0) / new A from m=0 epilogue (m=1)
        // kick prefetch of next B image pair into the other buffer (overlaps with MMA below)
        if (m + 1 < nmat) {
            const char* src = (const char*)(blob + (size_t)(m + 1) * 4352);
            uint32_t dstb = sb + ((m + 1) & 1 ? SM_B1 : SM_B0);
            for (int i = tid; i < 4352; i += 512)
                CP_ASYNC16(dstb + i * 16, src + i * 16);
            CP_COMMIT();
        }
        const uint32_t bAddrBase = sb + ((m & 1) ? SM_B1 : SM_B0) + bFragOff;

        float acc[2][4][4];
#pragma unroll
        for (int i = 0; i < 2; ++i)
#pragma unroll
            for (int j = 0; j < 4; ++j)
#pragma unroll
                for (int t = 0; t < 4; ++t) acc[i][j][t] = 0.f;

#pragma unroll 2
        for (int ks = 0; ks < 8; ++ks) {
            uint32_t af[2][4];
#pragma unroll
            for (int i = 0; i < 2; ++i) {
                uint32_t ra = aAddrBase + (uint32_t)i * 16 * ROWB + (uint32_t)ks * 32;
                LDM4(af[i][0], af[i][1], af[i][2], af[i][3], ra);
            }
            uint32_t bhi[4][2], blo[4][2];
#pragma unroll
            for (int jp = 0; jp < 2; ++jp) {
                uint32_t rb = bAddrBase + (uint32_t)jp * 16 * ROWB + (uint32_t)ks * 32;
                uint32_t r0, r1, r2, r3;
                LDM4(r0, r1, r2, r3, rb);
                bhi[2 * jp][0] = r0; bhi[2 * jp][1] = r1;
                bhi[2 * jp + 1][0] = r2; bhi[2 * jp + 1][1] = r3;
                LDM4(r0, r1, r2, r3, rb + HALFB);
                blo[2 * jp][0] = r0; blo[2 * jp][1] = r1;
                blo[2 * jp + 1][0] = r2; blo[2 * jp + 1][1] = r3;
            }
#pragma unroll
            for (int i = 0; i < 2; ++i)
#pragma unroll
                for (int j = 0; j < 4; ++j) {
                    MMA16816(acc[i][j], af[i], bhi[j]);
                    MMA16816(acc[i][j], af[i], blo[j]);
                }
        }

        // ---- epilogue ----
#pragma unroll
        for (int i = 0; i < 2; ++i) {
#pragma unroll
            for (int hrow = 0; hrow < 2; ++hrow) {
                int rloc = wr0 + i * 16 + (lane >> 2) + hrow * 8;   // local row 0..127
                int grow = row0 + rloc;
#pragma unroll
                for (int j = 0; j < 4; ++j) {
                    int c = wc0 + j * 8 + (lane & 3) * 2;
                    float o0 = acc[i][j][hrow * 2 + 0] + bias[m * 128 + c];
                    float o1 = acc[i][j][hrow * 2 + 1] + bias[m * 128 + c + 1];
                    if (m == 0) {
                        if (VARIANT == 0) {
                            o0 = fmaxf(o0, 0.f); o1 = fmaxf(o1, 0.f);
                        } else if (grow < nrows) {
                            float2 xv = __half22float2(*reinterpret_cast<const __half2*>(
                                xold + (size_t)grow * 128 + c));
                            o0 = alpha * o0 + (1.f - alpha) * xv.x;
                            o1 = alpha * o1 + (1.f - alpha) * xv.y;
                        }
                        __half2 h2 = __floats2half2_rn(o0, o1);
                        // feed the chained projections (becomes the new A tile)
                        *reinterpret_cast<__half2*>(smem + SM_A + (uint32_t)rloc * ROWB + c * 2) = h2;
                        if (VARIANT != 2 && grow < nrows)
                            *reinterpret_cast<__half2*>(c0 + (size_t)grow * 128 + c) = h2;
                    } else if (VARIANT == 2) {
                        if (c < 64 && grow < nrows)
                            *reinterpret_cast<float2*>(cf + (size_t)grow * 64 + c) = make_float2(o0, o1);
                    } else {
                        if (grow < nrows) {
                            __half* C = (m == 1) ? c1 : ((m == 2) ? c2 : c3);
                            *reinterpret_cast<__half2*>(C + (size_t)grow * 128 + c) =
                                __floats2half2_rn(o0, o1);
                        }
                    }
                }
            }
        }
        __syncthreads();  // m=0: A rewrite visible before m=1 ldmatrix; also WAR on B buffers
    }
}

// ---------------- CSR build ----------------
__global__ void hist2_kernel(const int* __restrict__ dstA, const int* __restrict__ dstB,
                             int* __restrict__ deg, int E, int eblk)
{
    int b = blockIdx.x;
    const int r = (b >= eblk) ? 1 : 0;
    if (r) b -= eblk;
    const int* dst = r ? dstB : dstA;
    int i = b * 256 + threadIdx.x;
    if (i < E) atomicAdd(&deg[r * NMAX + dst[i]], 1);
}

__global__ void psum_kernel(const int* __restrict__ deg, int* __restrict__ bsum,
                            int n, int nblk)
{
    __shared__ int ws[32];
    const int r = blockIdx.x / nblk;
    const int b = blockIdx.x % nblk;
    const int tid = threadIdx.x;  // 1024
    int i = b * 1024 + tid;
    int v = (i < n) ? deg[r * NMAX + i] : 0;
#pragma unroll
    for (int d = 16; d > 0; d >>= 1) v += __shfl_xor_sync(0xffffffffu, v, d);
    if ((tid & 31) == 0) ws[tid >> 5] = v;
    __syncthreads();
    if (tid < 32) {
        int x = ws[tid];
#pragma unroll
        for (int d = 16; d > 0; d >>= 1) x += __shfl_xor_sync(0xffffffffu, x, d);
        if (tid == 0) bsum[r * 1024 + b] = x;
    }
}

__global__ void bscan_kernel(int* __restrict__ bsum, int nblk)
{
    __shared__ int ws[32];
    const int tid = threadIdx.x;  // 1024
    for (int r = 0; r < 2; ++r) {
        int* a = bsum + r * 1024;
        int v = (tid < nblk) ? a[tid] : 0;
        int x = v;
#pragma unroll
        for (int d = 1; d < 32; d <<= 1) {
            int y = __shfl_up_sync(0xffffffffu, x, d);
            if ((tid & 31) >= d) x += y;
        }
        if ((tid & 31) == 31) ws[tid >> 5] = x;
        __syncthreads();
        if (tid < 32) {
            int w = ws[tid];
#pragma unroll
            for (int d = 1; d < 32; d <<= 1) {
                int y = __shfl_up_sync(0xffffffffu, w, d);
                if (tid >= d) w += y;
            }
            ws[tid] = w;
        }
        __syncthreads();
        int incl = x + ((tid >= 32) ? ws[(tid >> 5) - 1] : 0);
        if (tid < nblk) a[tid] = incl - v;  // exclusive
        __syncthreads();
    }
}

__global__ void blockscan_kernel(const int* __restrict__ deg, const int* __restrict__ bsum,
                                 int* __restrict__ off, int* __restrict__ cur,
                                 int n, int nblk)
{
    __shared__ int ws[32];
    const int r = blockIdx.x / nblk;
    const int b = blockIdx.x % nblk;
    const int tid = threadIdx.x;  // 1024
    const int i = b * 1024 + tid;
    int v = (i < n) ? deg[r * NMAX + i] : 0;
    int x = v;
#pragma unroll
    for (int d = 1; d < 32; d <<= 1) {
        int y = __shfl_up_sync(0xffffffffu, x, d);
        if ((tid & 31) >= d) x += y;
    }
    if ((tid & 31) == 31) ws[tid >> 5] = x;
    __syncthreads();
    if (tid < 32) {
        int w = ws[tid];
#pragma unroll
        for (int d = 1; d < 32; d <<= 1) {
            int y = __shfl_up_sync(0xffffffffu, w, d);
            if (tid >= d) w += y;
        }
        ws[tid] = w;
    }
    __syncthreads();
    int incl = x + ((tid >= 32) ? ws[(tid >> 5) - 1] : 0) + bsum[r * 1024 + b];
    if (i < n) {
        off[r * (NMAX + 1) + i + 1] = incl;
        cur[r * NMAX + i] = incl - v;  // == off[i] (exclusive prefix)
    }
    if (b == 0 && tid == 0) off[r * (NMAX + 1)] = 0;
}

__global__ void fill2_kernel(const int* __restrict__ eA, const int* __restrict__ eB,
                             int* __restrict__ cur, int* __restrict__ csrc, int E, int eblk)
{
    int b = blockIdx.x;
    const int r = (b >= eblk) ? 1 : 0;
    if (r) b -= eblk;
    const int* ep = r ? eB : eA;
    int i = b * 256 + threadIdx.x;
    if (i < E) {
        int p = atomicAdd(&cur[r * NMAX + ep[E + i]], 1);
        csrc[r * EMAX + p] = ep[i];
    }
}

// ---------------- flash attention: warp per dst node, single relation per launch ----------------
__device__ __forceinline__ float4 ldh4(const __half* p) {
    uint2 raw = *reinterpret_cast<const uint2*>(p);
    __half2 h0 = *reinterpret_cast<const __half2*>(&raw.x);
    __half2 h1 = *reinterpret_cast<const __half2*>(&raw.y);
    float2 a = __half22float2(h0), b = __half22float2(h1);
    return make_float4(a.x, a.y, b.x, b.y);
}

__global__ void attn_fused(const int* __restrict__ offr, const int* __restrict__ csr,
                           const __half* __restrict__ q, const __half* __restrict__ kr,
                           const __half* __restrict__ vr,
                           __half* __restrict__ out, int n)
{
    int w = (blockIdx.x * blockDim.x + threadIdx.x) >> 5;
    int lane = threadIdx.x & 31;
    if (w >= n) return;

    const int beg = offr[w], end = offr[w + 1];
    float4 q4 = ldh4(q + (size_t)w * HIDC + lane * 4);

    float m = -INFINITY, ss = 0.f;
    float4 acc = make_float4(0.f, 0.f, 0.f, 0.f);
    int i = beg;
    for (; i + 2 <= end; i += 2) {
        int s0 = csr[i], s1 = csr[i + 1];
        float4 k0 = ldh4(kr + (size_t)s0 * HIDC + lane * 4);
        float4 v0 = ldh4(vr + (size_t)s0 * HIDC + lane * 4);
        float4 k1 = ldh4(kr + (size_t)s1 * HIDC + lane * 4);
        float4 v1 = ldh4(vr + (size_t)s1 * HIDC + lane * 4);
        float p0 = q4.x * k0.x + q4.y * k0.y + q4.z * k0.z + q4.w * k0.w;
        float p1 = q4.x * k1.x + q4.y * k1.y + q4.z * k1.z + q4.w * k1.w;
        p0 += __shfl_xor_sync(0xffffffffu, p0, 1);
        p1 += __shfl_xor_sync(0xffffffffu, p1, 1);
        p0 += __shfl_xor_sync(0xffffffffu, p0, 2);
        p1 += __shfl_xor_sync(0xffffffffu, p1, 2);
        float mn = fmaxf(m, fmaxf(p0, p1));
        float corr = __expf(m - mn);
        float w0 = __expf(p0 - mn);
        float w1 = __expf(p1 - mn);
        ss = ss * corr + w0 + w1;
        acc.x = acc.x * corr + w0 * v0.x + w1 * v1.x;
        acc.y = acc.y * corr + w0 * v0.y + w1 * v1.y;
        acc.z = acc.z * corr + w0 * v0.z + w1 * v1.z;
        acc.w = acc.w * corr + w0 * v0.w + w1 * v1.w;
        m = mn;
    }
    if (i < end) {
        int s = csr[i];
        float4 k4 = ldh4(kr + (size_t)s * HIDC + lane * 4);
        float4 v4 = ldh4(vr + (size_t)s * HIDC + lane * 4);
        float p = q4.x * k4.x + q4.y * k4.y + q4.z * k4.z + q4.w * k4.w;
        p += __shfl_xor_sync(0xffffffffu, p, 1);
        p += __shfl_xor_sync(0xffffffffu, p, 2);
        float mn = fmaxf(m, p);
        float corr = __expf(m - mn);
        float wgt = __expf(p - mn);
        ss = ss * corr + wgt;
        acc.x = acc.x * corr + wgt * v4.x;
        acc.y = acc.y * corr + wgt * v4.y;
        acc.z = acc.z * corr + wgt * v4.z;
        acc.w = acc.w * corr + wgt * v4.w;
        m = mn;
    }
    const float is = 1.f / (ss + 1e-16f);
    __half2 o0 = __floats2half2_rn(acc.x * is, acc.y * is);
    __half2 o1 = __floats2half2_rn(acc.z * is, acc.w * is);
    uint2 packed;
    packed.x = *reinterpret_cast<uint32_t*>(&o0);
    packed.y = *reinterpret_cast<uint32_t*>(&o1);
    *reinterpret_cast<uint2*>(out + (size_t)w * HIDC + lane * 4) = packed;
}

// ---------------- launch ----------------
extern "C" void kernel_launch(void* const* d_in, const int* in_sizes, int n_in,
                              void* d_out, int out_size)
{
    const float* x_cpd    = (const float*)d_in[0];
    const float* x_ko     = (const float*)d_in[1];
    const int*   e_c2k    = (const int*)d_in[2];
    const int*   e_k2c    = (const int*)d_in[3];
    const float* w_in_cpd = (const float*)d_in[4];
    const float* b_in_cpd = (const float*)d_in[5];
    const float* w_in_ko  = (const float*)d_in[6];
    const float* b_in_ko  = (const float*)d_in[7];

    const float *w_k, *b_k, *w_q, *b_q, *w_v, *b_v;
    const float *a_rel, *m_rel, *p_rel, *w_a, *b_a, *skip, *w_out, *b_out;
    if (in_sizes[9] == 2 * 2 * HIDC) {
        w_k = (const float*)d_in[8];   b_k = (const float*)d_in[9];
        w_q = (const float*)d_in[10];  b_q = (const float*)d_in[11];
        w_v = (const float*)d_in[12];  b_v = (const float*)d_in[13];
        a_rel = (const float*)d_in[14]; m_rel = (const float*)d_in[15];
        p_rel = (const float*)d_in[16];
        w_a = (const float*)d_in[17];  b_a = (const float*)d_in[18];
        skip = (const float*)d_in[19];
        w_out = (const float*)d_in[20]; b_out = (const float*)d_in[21];
    } else {
        w_k = (const float*)d_in[8];   w_q = (const float*)d_in[9];
        w_v = (const float*)d_in[10];  w_a = (const float*)d_in[11];
        b_k = (const float*)d_in[12];  b_q = (const float*)d_in[13];
        b_v = (const float*)d_in[14];  b_a = (const float*)d_in[15];
        a_rel = (const float*)d_in[16]; m_rel = (const float*)d_in[17];
        p_rel = (const float*)d_in[18]; skip = (const float*)d_in[19];
        w_out = (const float*)d_in[20]; b_out = (const float*)d_in[21];
    }

    const int N = in_sizes[0] / 64;
    const int E = in_sizes[2] / 2;

    void* p;
    __half *xA, *xB, *qh, *kh, *vh, *att;
    int *deg, *off, *cur, *csrc, *bsum;
    uint4* wblob;
    float* biasP;
    cudaGetSymbolAddress(&p, g_xA);  xA  = (__half*)p;
    cudaGetSymbolAddress(&p, g_xB);  xB  = (__half*)p;
    cudaGetSymbolAddress(&p, g_qh);  qh  = (__half*)p;
    cudaGetSymbolAddress(&p, g_kh);  kh  = (__half*)p;
    cudaGetSymbolAddress(&p, g_vh);  vh  = (__half*)p;
    cudaGetSymbolAddress(&p, g_att); att = (__half*)p;
    cudaGetSymbolAddress(&p, g_deg); deg = (int*)p;
    cudaGetSymbolAddress(&p, g_off); off = (int*)p;
    cudaGetSymbolAddress(&p, g_cur); cur = (int*)p;
    cudaGetSymbolAddress(&p, g_csrc); csrc = (int*)p;
    cudaGetSymbolAddress(&p, g_bsum); bsum = (int*)p;
    cudaGetSymbolAddress(&p, g_wblob); wblob = (uint4*)p;
    cudaGetSymbolAddress(&p, g_biasP); biasP = (float*)p;

    const size_t NSTR = (size_t)NMAX * HIDC;

    // ---- weight prep jobs, grouped per fused launch set ----
    PrepArgs pa;
    auto setjob = [&](int idx, const float* W, const float* b, const float* rel,
                      const float* psc, int kin, int nout) {
        pa.j[idx].W = W; pa.j[idx].b = b; pa.j[idx].rel = rel; pa.j[idx].psc = psc;
        pa.j[idx].kin = kin; pa.j[idx].nout = nout;
        pa.j[idx].blob = wblob + (size_t)idx * 4352;
        pa.j[idx].bias = biasP + (size_t)idx * 128;
    };
    auto jq = [&](int idx, int l, int t) {
        int lt = l * 2 + t;
        setjob(idx, w_q + (size_t)lt * HIDC * HIDC, b_q + (size_t)lt * HIDC,
               nullptr, p_rel + (size_t)(l * 2 + (1 - t)) * NH, 128, 128);
    };
    auto jk = [&](int idx, int l, int t) {
        int lt = l * 2 + t;
        setjob(idx, w_k + (size_t)lt * HIDC * HIDC, b_k + (size_t)lt * HIDC,
               a_rel + (size_t)lt * NH * HD * HD, nullptr, 128, 128);
    };
    auto jv = [&](int idx, int l, int t) {
        int lt = l * 2 + t;
        setjob(idx, w_v + (size_t)lt * HIDC * HIDC, b_v + (size_t)lt * HIDC,
               m_rel + (size_t)lt * NH * HD * HD, nullptr, 128, 128);
    };
    auto ja = [&](int idx, int l, int t) {
        int lt = l * 2 + t;
        setjob(idx, w_a + (size_t)lt * HIDC * HIDC, b_a + (size_t)lt * HIDC,
               nullptr, nullptr, 128, 128);
    };
    // set A: [in, q0, k0, v0] per type
    setjob(0, w_in_cpd, b_in_cpd, nullptr, nullptr, 64, 128);
    jq(1, 0, 0); jk(2, 0, 0); jv(3, 0, 0);
    setjob(4, w_in_ko, b_in_ko, nullptr, nullptr, 128, 128);
    jq(5, 0, 1); jk(6, 0, 1); jv(7, 0, 1);
    // set B: [a(l0), q1, k1, v1] per type
    ja(8, 0, 0);  jq(9, 1, 0);  jk(10, 1, 0); jv(11, 1, 0);
    ja(12, 0, 1); jq(13, 1, 1); jk(14, 1, 1); jv(15, 1, 1);
    // set C: [a(l1), out] per type
    ja(16, 1, 0); setjob(17, w_out, b_out, nullptr, nullptr, 128, 64);
    ja(18, 1, 1); setjob(19, w_out, b_out, nullptr, nullptr, 128, 64);

    cudaFuncSetAttribute(gemm_chain<0>, cudaFuncAttributeMaxDynamicSharedMemorySize, SMEM_TOT);
    cudaFuncSetAttribute(gemm_chain<1>, cudaFuncAttributeMaxDynamicSharedMemorySize, SMEM_TOT);
    cudaFuncSetAttribute(gemm_chain<2>, cudaFuncAttributeMaxDynamicSharedMemorySize, SMEM_TOT);

    const int gB = (N + 127) / 128;
    const int eblk = (E + 255) / 256;
    const int awgrid = (N + 7) / 8;
    const int nblk = (N + 1023) / 1024;

    prep_kernel<<<20, 256>>>(pa);

    // CSR build (independent of features)
    cudaMemsetAsync(deg, 0, sizeof(int) * 2 * NMAX);
    hist2_kernel<<<2 * eblk, 256>>>(e_c2k + E, e_k2c + E, deg, E, eblk);
    psum_kernel<<<2 * nblk, 1024>>>(deg, bsum, N, nblk);
    bscan_kernel<<<1, 1024>>>(bsum, nblk);
    blockscan_kernel<<<2 * nblk, 1024>>>(deg, bsum, off, cur, N, nblk);
    fill2_kernel<<<2 * eblk, 256>>>(e_c2k, e_k2c, cur, csrc, E, eblk);

    // set A: in-proj (relu) chained into qkv layer 0
    gemm_chain<0><<<2 * gB, 512, SMEM_TOT>>>(
        x_cpd, 64, wblob, biasP, xA, qh, kh, vh, nullptr,
        N, nullptr, nullptr,
        gB, 128, (ptrdiff_t)(x_ko - x_cpd), (size_t)4 * 4352, 4 * 128, NSTR, 0, 0);

    // attention layer 0
    attn_fused<<<awgrid, 256>>>(off, csrc, qh + NSTR, kh, vh, att + NSTR, N);
    attn_fused<<<awgrid, 256>>>(off + (NMAX + 1), csrc + EMAX, qh, kh + NSTR, vh + NSTR, att, N);

    // set B: blend layer0 (x1 = s*gelu(att)@w_a + (1-s)*x0) chained into qkv layer 1
    gemm_chain<1><<<2 * gB, 512, SMEM_TOT>>>(
        (const float*)att, 128, wblob + (size_t)8 * 4352, biasP + (size_t)8 * 128,
        xB, qh, kh, vh, nullptr,
        N, xA, skip,
        gB, 128, (ptrdiff_t)NSTR, (size_t)4 * 4352, 4 * 128, NSTR, 1, 0);

    // attention layer 1
    attn_fused<<<awgrid, 256>>>(off, csrc, qh + NSTR, kh, vh, att + NSTR, N);
    attn_fused<<<awgrid, 256>>>(off + (NMAX + 1), csrc + EMAX, qh, kh + NSTR, vh + NSTR, att, N);

    // set C: blend layer1 chained into final projection (fp32 out, nout=64)
    float* out = (float*)d_out;
    gemm_chain<2><<<2 * gB, 512, SMEM_TOT>>>(
        (const float*)att, 128, wblob + (size_t)16 * 4352, biasP + (size_t)16 * 128,
        nullptr, nullptr, nullptr, nullptr, out,
        N, xB, skip + 2,
        gB, 128, (ptrdiff_t)NSTR, (size_t)2 * 4352, 2 * 128, NSTR, 1, (size_t)N * 64);
}